// round 2
// baseline (speedup 1.0000x reference)
#include <cuda_runtime.h>
#include <cuda_bf16.h>
#include <math.h>

// ---------------- problem constants ----------------
#define Bb 4
#define Ss 512
#define Hh 512
#define NHh 8
#define DHh 64
#define Tt 3
#define DTS 170
#define BS 2048            // B*S
#define H3 1536            // 3*H
#define EPSF 1e-5f

// ---------------- static scratch ----------------
__device__ float g_mask[(size_t)Tt * Bb * Ss * Ss];
__device__ float g_qkv[(size_t)BS * H3];
__device__ float g_scores[(size_t)Bb * NHh * Ss * Ss];
__device__ float g_att[(size_t)BS * Hh];
__device__ float g_combined[(size_t)BS * Tt * Hh];
__device__ float g_t0[(size_t)BS * 2048];
__device__ float g_t1[(size_t)BS * Hh];
__device__ float g_logits[(size_t)BS * 4];
__device__ float g_weighted[(size_t)BS * Hh];
__device__ float g_sa[(size_t)BS * Hh];
__device__ float g_h1[(size_t)BS * Hh];
__device__ float g_h2[(size_t)BS * Hh];

__device__ __forceinline__ float gelu_exact(float x) {
    return 0.5f * x * (1.0f + erff(x * 0.70710678118654752f));
}

enum { ACT_NONE = 0, ACT_GELU = 1 };

// ================= 128x128x16 SGEMM, 8x8 microtile, 256 threads =================
// Requires: M % 128 == 0, N % 128 == 0, K % 16 == 0 at all call sites.
// C[M,N] = alpha * A[M,K] @ (TB ? B[N,K]^T : B[K,N]) + bias[N], optional GELU.
template <bool TB, int ACT>
__device__ __forceinline__ void gemm128_body(
    const float* __restrict__ A, const float* __restrict__ B,
    const float* __restrict__ bias, float* __restrict__ C,
    int K, int lda, int ldb, int ldc, float alpha,
    int bm, int bn)
{
    __shared__ float As[16][132];
    __shared__ float Bs[16][132];
    const int tid = threadIdx.x;       // 0..255
    const int tx  = tid & 15;
    const int ty  = tid >> 4;
    const int ty8 = ty << 3;
    const int tx8 = tx << 3;

    float acc[8][8];
#pragma unroll
    for (int i = 0; i < 8; i++)
#pragma unroll
        for (int j = 0; j < 8; j++) acc[i][j] = 0.f;

    for (int k0 = 0; k0 < K; k0 += 16) {
        // ---- A tile: 128 rows x 16 k -> As[k][m] (transposed) ----
#pragma unroll
        for (int j = 0; j < 2; j++) {
            int i  = tid + 256 * j;
            int r  = i >> 2;
            int kq = (i & 3) << 2;
            float4 a = *(const float4*)(A + (size_t)(bm + r) * lda + k0 + kq);
            As[kq + 0][r] = a.x;
            As[kq + 1][r] = a.y;
            As[kq + 2][r] = a.z;
            As[kq + 3][r] = a.w;
        }
        // ---- B tile ----
        if (TB) {
#pragma unroll
            for (int j = 0; j < 2; j++) {
                int i  = tid + 256 * j;
                int r  = i >> 2;                 // n index
                int kq = (i & 3) << 2;
                float4 b = *(const float4*)(B + (size_t)(bn + r) * ldb + k0 + kq);
                Bs[kq + 0][r] = b.x;
                Bs[kq + 1][r] = b.y;
                Bs[kq + 2][r] = b.z;
                Bs[kq + 3][r] = b.w;
            }
        } else {
#pragma unroll
            for (int j = 0; j < 2; j++) {
                int i  = tid + 256 * j;
                int kk = i >> 5;                 // 0..15
                int n4 = (i & 31) << 2;          // 0..124
                float4 b = *(const float4*)(B + (size_t)(k0 + kk) * ldb + bn + n4);
                *(float4*)&Bs[kk][n4] = b;
            }
        }
        __syncthreads();

#pragma unroll
        for (int kk = 0; kk < 16; kk++) {
            float ar[8], br[8];
            *(float4*)&ar[0] = *(const float4*)&As[kk][ty8];
            *(float4*)&ar[4] = *(const float4*)&As[kk][ty8 + 4];
            *(float4*)&br[0] = *(const float4*)&Bs[kk][tx8];
            *(float4*)&br[4] = *(const float4*)&Bs[kk][tx8 + 4];
#pragma unroll
            for (int i = 0; i < 8; i++)
#pragma unroll
                for (int j = 0; j < 8; j++)
                    acc[i][j] += ar[i] * br[j];
        }
        __syncthreads();
    }

    // ---- epilogue ----
    float bv[8];
#pragma unroll
    for (int j = 0; j < 8; j++) bv[j] = bias ? bias[bn + tx8 + j] : 0.f;

#pragma unroll
    for (int i = 0; i < 8; i++) {
        float* cp = C + (size_t)(bm + ty8 + i) * ldc + bn + tx8;
        float v[8];
#pragma unroll
        for (int j = 0; j < 8; j++) {
            float t = acc[i][j] * alpha + bv[j];
            if (ACT == ACT_GELU) t = gelu_exact(t);
            v[j] = t;
        }
        *(float4*)&cp[0] = make_float4(v[0], v[1], v[2], v[3]);
        *(float4*)&cp[4] = make_float4(v[4], v[5], v[6], v[7]);
    }
}

template <int ACT>
__global__ void gemm128_nn(const float* __restrict__ A, const float* __restrict__ B,
                           const float* __restrict__ bias, float* __restrict__ C,
                           int K, int lda, int ldb, int ldc, float alpha)
{
    gemm128_body<false, ACT>(A, B, bias, C, K, lda, ldb, ldc, alpha,
                             blockIdx.y * 128, blockIdx.x * 128);
}

// scores[b,h,q,k] = (1/8) * sum_d Q[b,q,h,d] * K[b,k,h,d]   (M=N=512, K=64)
__global__ void attn_scores_kernel(const float* __restrict__ qkv, float* __restrict__ scores)
{
    int z = blockIdx.z;
    int b = z >> 3, h = z & 7;
    const float* Aq = qkv + (size_t)b * Ss * H3 + h * DHh;
    const float* Bk = qkv + (size_t)b * Ss * H3 + Hh + h * DHh;
    float* C = scores + (size_t)z * Ss * Ss;
    gemm128_body<true, ACT_NONE>(Aq, Bk, nullptr, C, DHh, H3, H3, Ss, 0.125f,
                                 blockIdx.y * 128, blockIdx.x * 128);
}

// ================= 64x64 SGEMM (for skinny N) =================
template <bool TB, int ACT>
__device__ __forceinline__ void gemm_body(
    const float* __restrict__ A, const float* __restrict__ B,
    const float* __restrict__ bias, float* __restrict__ C,
    int M, int N, int K, int lda, int ldb, int ldc, float alpha,
    int bm, int bn)
{
    __shared__ float As[16][68];
    __shared__ float Bs[16][68];
    const int tid = threadIdx.x;
    const int tx  = tid & 15;
    const int ty  = tid >> 4;

    float acc[4][4];
#pragma unroll
    for (int i = 0; i < 4; i++)
#pragma unroll
        for (int j = 0; j < 4; j++) acc[i][j] = 0.f;

    for (int k0 = 0; k0 < K; k0 += 16) {
        {
            int r  = tid >> 2;
            int kq = (tid & 3) << 2;
            int gr = bm + r;
            float4 a = make_float4(0.f, 0.f, 0.f, 0.f);
            if (gr < M)
                a = *(const float4*)(A + (size_t)gr * lda + k0 + kq);
            As[kq + 0][r] = a.x;
            As[kq + 1][r] = a.y;
            As[kq + 2][r] = a.z;
            As[kq + 3][r] = a.w;
        }
        if (TB) {
            int r  = tid >> 2;
            int kq = (tid & 3) << 2;
            int gn = bn + r;
            float4 bvv = make_float4(0.f, 0.f, 0.f, 0.f);
            if (gn < N)
                bvv = *(const float4*)(B + (size_t)gn * ldb + k0 + kq);
            Bs[kq + 0][r] = bvv.x;
            Bs[kq + 1][r] = bvv.y;
            Bs[kq + 2][r] = bvv.z;
            Bs[kq + 3][r] = bvv.w;
        } else {
            int kk = tid >> 4;
            int n4 = (tid & 15) << 2;
            int gn = bn + n4;
            float t0 = 0.f, t1 = 0.f, t2 = 0.f, t3 = 0.f;
            if (gn + 3 < N) {
                float4 bvv = *(const float4*)(B + (size_t)(k0 + kk) * ldb + gn);
                t0 = bvv.x; t1 = bvv.y; t2 = bvv.z; t3 = bvv.w;
            } else {
                if (gn + 0 < N) t0 = B[(size_t)(k0 + kk) * ldb + gn + 0];
                if (gn + 1 < N) t1 = B[(size_t)(k0 + kk) * ldb + gn + 1];
                if (gn + 2 < N) t2 = B[(size_t)(k0 + kk) * ldb + gn + 2];
                if (gn + 3 < N) t3 = B[(size_t)(k0 + kk) * ldb + gn + 3];
            }
            Bs[kk][n4 + 0] = t0;
            Bs[kk][n4 + 1] = t1;
            Bs[kk][n4 + 2] = t2;
            Bs[kk][n4 + 3] = t3;
        }
        __syncthreads();

#pragma unroll
        for (int kk = 0; kk < 16; kk++) {
            float4 av = *(const float4*)&As[kk][ty << 2];
            float4 bvv = *(const float4*)&Bs[kk][tx << 2];
            acc[0][0] += av.x * bvv.x; acc[0][1] += av.x * bvv.y;
            acc[0][2] += av.x * bvv.z; acc[0][3] += av.x * bvv.w;
            acc[1][0] += av.y * bvv.x; acc[1][1] += av.y * bvv.y;
            acc[1][2] += av.y * bvv.z; acc[1][3] += av.y * bvv.w;
            acc[2][0] += av.z * bvv.x; acc[2][1] += av.z * bvv.y;
            acc[2][2] += av.z * bvv.z; acc[2][3] += av.z * bvv.w;
            acc[3][0] += av.w * bvv.x; acc[3][1] += av.w * bvv.y;
            acc[3][2] += av.w * bvv.z; acc[3][3] += av.w * bvv.w;
        }
        __syncthreads();
    }

#pragma unroll
    for (int i = 0; i < 4; i++) {
        int gm = bm + (ty << 2) + i;
        if (gm >= M) continue;
#pragma unroll
        for (int j = 0; j < 4; j++) {
            int gn = bn + (tx << 2) + j;
            if (gn >= N) continue;
            float v = acc[i][j] * alpha;
            if (bias) v += bias[gn];
            if (ACT == ACT_GELU) v = gelu_exact(v);
            C[(size_t)gm * ldc + gn] = v;
        }
    }
}

template <int ACT>
__global__ void gemm_nn(const float* __restrict__ A, const float* __restrict__ B,
                        const float* __restrict__ bias, float* __restrict__ C,
                        int M, int N, int K, int lda, int ldb, int ldc, float alpha)
{
    gemm_body<false, ACT>(A, B, bias, C, M, N, K, lda, ldb, ldc, alpha,
                          blockIdx.y * 64, blockIdx.x * 64);
}

// O[b,q,h*64+d] = sum_k P[b,h,q,k] * V[b,k,h,d]
__global__ void attn_pv_kernel(const float* __restrict__ P, const float* __restrict__ qkv,
                               float* __restrict__ O)
{
    int z = blockIdx.z;
    int b = z >> 3, h = z & 7;
    const float* Ap = P + (size_t)z * Ss * Ss;
    const float* Bv = qkv + (size_t)b * Ss * H3 + 2 * Hh + h * DHh;
    float* C = O + (size_t)b * Ss * Hh + h * DHh;
    gemm_body<false, ACT_NONE>(Ap, Bv, nullptr, C, Ss, DHh, Ss, Ss, H3, Hh, 1.0f,
                               blockIdx.y * 64, blockIdx.x * 64);
}

// ================= mask kernel: one warp per (b,q,k) =================
__global__ void mask_kernel(const float* __restrict__ ts,
                            const float* __restrict__ enc_W, const float* __restrict__ enc_b,
                            const float* __restrict__ lng, const float* __restrict__ lnb,
                            float* __restrict__ mask)
{
    __shared__ float sW0[Tt][DTS], sW1[Tt][DTS], sB[Tt][DTS], sG[Tt][DTS], sBe[Tt][DTS];
    for (int idx = threadIdx.x; idx < Tt * DTS; idx += blockDim.x) {
        int i = idx / DTS, d = idx % DTS;
        sW0[i][d] = enc_W[i * 2 * DTS + d];
        sW1[i][d] = enc_W[i * 2 * DTS + DTS + d];
        sB[i][d]  = enc_b[idx];
        sG[i][d]  = lng[idx];
        sBe[i][d] = lnb[idx];
    }
    __syncthreads();

    int warp = blockIdx.x * (blockDim.x >> 5) + (threadIdx.x >> 5);
    int lane = threadIdx.x & 31;
    int k = warp & (Ss - 1);
    int q = (warp >> 9) & (Ss - 1);
    int b = warp >> 18;

    float dt  = ts[b * Ss + q] - ts[b * Ss + k];
    float dir = (dt > 0.f) ? 1.f : ((dt < 0.f) ? -1.f : 0.f);
    float am  = log1pf(fabsf(dt) * (1.0f / 3600.0f));

    float scale = 1.0f;
#pragma unroll
    for (int i = 0; i < Tt; i++) {
        float mag = am * scale;
        float v[6];
        float s1 = 0.f, s2 = 0.f;
#pragma unroll
        for (int j = 0; j < 6; j++) {
            int d = lane + 32 * j;
            float val = 0.f;
            if (d < DTS) val = dir * sW0[i][d] + mag * sW1[i][d] + sB[i][d];
            v[j] = val;
            s1 += val;
            s2 += val * val;
        }
#pragma unroll
        for (int o = 16; o > 0; o >>= 1) {
            s1 += __shfl_xor_sync(0xffffffffu, s1, o);
            s2 += __shfl_xor_sync(0xffffffffu, s2, o);
        }
        float mean = s1 * (1.0f / DTS);
        float var  = s2 * (1.0f / DTS) - mean * mean;
        float rstd = rsqrtf(var + EPSF);
        float g = 0.f;
#pragma unroll
        for (int j = 0; j < 6; j++) {
            int d = lane + 32 * j;
            if (d < DTS) {
                float t = (v[j] - mean) * rstd * sG[i][d] + sBe[i][d];
                g += gelu_exact(t);
            }
        }
#pragma unroll
        for (int o = 16; o > 0; o >>= 1) g += __shfl_xor_sync(0xffffffffu, g, o);
        if (lane == 0)
            mask[(size_t)i * (Bb * Ss * Ss) + warp] = g * (1.0f / DTS);
        scale *= 0.1f;
    }
}

// ================= row softmax with optional additive mask (in place) =================
__global__ void softmax_mask_kernel(float* __restrict__ scores, const float* __restrict__ mask)
{
    __shared__ float sred[8];
    __shared__ float sval;
    int row = blockIdx.x;
    int tid = threadIdx.x;
    float* sr = scores + (size_t)row * Ss;

    float m0 = 0.f, m1 = 0.f;
    if (mask) {
        int q = row & (Ss - 1);
        int b = row >> 12;
        const float* mr = mask + ((size_t)(b * Ss + q)) * Ss;
        m0 = mr[tid];
        m1 = mr[tid + 256];
    }
    float v0 = sr[tid] + m0;
    float v1 = sr[tid + 256] + m1;

    float mx = fmaxf(v0, v1);
#pragma unroll
    for (int o = 16; o > 0; o >>= 1) mx = fmaxf(mx, __shfl_xor_sync(0xffffffffu, mx, o));
    if ((tid & 31) == 0) sred[tid >> 5] = mx;
    __syncthreads();
    if (tid == 0) {
        float m = sred[0];
        for (int i = 1; i < 8; i++) m = fmaxf(m, sred[i]);
        sval = m;
    }
    __syncthreads();
    mx = sval;

    float e0 = __expf(v0 - mx), e1 = __expf(v1 - mx);
    float s = e0 + e1;
#pragma unroll
    for (int o = 16; o > 0; o >>= 1) s += __shfl_xor_sync(0xffffffffu, s, o);
    if ((tid & 31) == 0) sred[tid >> 5] = s;
    __syncthreads();
    if (tid == 0) {
        float t = 0.f;
        for (int i = 0; i < 8; i++) t += sred[i];
        sval = t;
    }
    __syncthreads();
    float inv = 1.0f / sval;
    sr[tid]       = e0 * inv;
    sr[tid + 256] = e1 * inv;
}

// ================= LayerNorm (+optional residual, +optional gelu) =================
template <bool GELU>
__global__ void ln_kernel(const float* __restrict__ x, const float* __restrict__ res,
                          const float* __restrict__ g, const float* __restrict__ b,
                          float* __restrict__ y, int width)
{
    __shared__ float sred[8], sred2[8];
    __shared__ float smv[2];
    int row = blockIdx.x, tid = threadIdx.x;
    const float* xr = x + (size_t)row * width;
    const float* rr = res ? res + (size_t)row * width : nullptr;

    float s1 = 0.f, s2 = 0.f;
    for (int c = tid; c < width; c += blockDim.x) {
        float v = xr[c] + (rr ? rr[c] : 0.f);
        s1 += v;
        s2 += v * v;
    }
#pragma unroll
    for (int o = 16; o > 0; o >>= 1) {
        s1 += __shfl_xor_sync(0xffffffffu, s1, o);
        s2 += __shfl_xor_sync(0xffffffffu, s2, o);
    }
    if ((tid & 31) == 0) { sred[tid >> 5] = s1; sred2[tid >> 5] = s2; }
    __syncthreads();
    if (tid == 0) {
        float a = 0.f, c2 = 0.f;
        int nw = blockDim.x >> 5;
        for (int i = 0; i < nw; i++) { a += sred[i]; c2 += sred2[i]; }
        float mean = a / width;
        float var  = c2 / width - mean * mean;
        smv[0] = mean;
        smv[1] = rsqrtf(var + EPSF);
    }
    __syncthreads();
    float mean = smv[0], rstd = smv[1];
    for (int c = tid; c < width; c += blockDim.x) {
        float v = xr[c] + (rr ? rr[c] : 0.f);
        float t = (v - mean) * rstd * g[c] + b[c];
        if (GELU) t = gelu_exact(t);
        y[(size_t)row * width + c] = t;
    }
}

// ================= mixer softmax-weighted combine =================
__global__ void weighted_kernel(const float* __restrict__ combined,
                                const float* __restrict__ logits,
                                float* __restrict__ out)
{
    int idx = blockIdx.x * blockDim.x + threadIdx.x;
    int r = idx >> 9;
    int c = idx & (Hh - 1);
    float l0 = logits[r * 3 + 0];
    float l1 = logits[r * 3 + 1];
    float l2 = logits[r * 3 + 2];
    float mx = fmaxf(l0, fmaxf(l1, l2));
    float e0 = expf(l0 - mx), e1 = expf(l1 - mx), e2 = expf(l2 - mx);
    float inv = 1.0f / (e0 + e1 + e2);
    const float* cr = combined + (size_t)r * (Tt * Hh);
    out[idx] = (e0 * cr[c] + e1 * cr[Hh + c] + e2 * cr[2 * Hh + c]) * inv;
}

// ================= host-side orchestration =================
extern "C" void kernel_launch(void* const* d_in, const int* in_sizes, int n_in,
                              void* d_out, int out_size)
{
    const float* x          = (const float*)d_in[0];
    const float* ts         = (const float*)d_in[1];
    const float* enc_W      = (const float*)d_in[2];
    const float* enc_b      = (const float*)d_in[3];
    const float* enc_ln_g   = (const float*)d_in[4];
    const float* enc_ln_b   = (const float*)d_in[5];
    const float* qkv_W      = (const float*)d_in[6];
    const float* qkv_b      = (const float*)d_in[7];
    const float* attn_out_W = (const float*)d_in[8];
    const float* attn_out_b = (const float*)d_in[9];
    const float* mixer_W1   = (const float*)d_in[10];
    const float* mixer_b1   = (const float*)d_in[11];
    const float* mixer_ln_g = (const float*)d_in[12];
    const float* mixer_ln_b = (const float*)d_in[13];
    const float* mixer_W2   = (const float*)d_in[14];
    const float* mixer_b2   = (const float*)d_in[15];
    const float* el_qkv_W   = (const float*)d_in[16];
    const float* el_qkv_b   = (const float*)d_in[17];
    const float* el_out_W   = (const float*)d_in[18];
    const float* el_out_b   = (const float*)d_in[19];
    const float* el_ln1_g   = (const float*)d_in[20];
    const float* el_ln1_b   = (const float*)d_in[21];
    const float* el_ff_W1   = (const float*)d_in[22];
    const float* el_ff_b1   = (const float*)d_in[23];
    const float* el_ff_W2   = (const float*)d_in[24];
    const float* el_ff_b2   = (const float*)d_in[25];
    const float* el_ln2_g   = (const float*)d_in[26];
    const float* el_ln2_b   = (const float*)d_in[27];
    const float* op_W       = (const float*)d_in[28];
    const float* op_b       = (const float*)d_in[29];
    const float* op_ln_g    = (const float*)d_in[30];
    const float* op_ln_b    = (const float*)d_in[31];
    float* out = (float*)d_out;

    float *mask, *qkv, *scores, *att, *combined, *t0, *t1, *logits, *weighted, *sa, *h1, *h2;
    cudaGetSymbolAddress((void**)&mask, g_mask);
    cudaGetSymbolAddress((void**)&qkv, g_qkv);
    cudaGetSymbolAddress((void**)&scores, g_scores);
    cudaGetSymbolAddress((void**)&att, g_att);
    cudaGetSymbolAddress((void**)&combined, g_combined);
    cudaGetSymbolAddress((void**)&t0, g_t0);
    cudaGetSymbolAddress((void**)&t1, g_t1);
    cudaGetSymbolAddress((void**)&logits, g_logits);
    cudaGetSymbolAddress((void**)&weighted, g_weighted);
    cudaGetSymbolAddress((void**)&sa, g_sa);
    cudaGetSymbolAddress((void**)&h1, g_h1);
    cudaGetSymbolAddress((void**)&h2, g_h2);

    // 1) per-timescale additive attention masks
    mask_kernel<<<(Bb * Ss * Ss) / 8, 256>>>(ts, enc_W, enc_b, enc_ln_g, enc_ln_b, mask);

    // 2) per-timescale MHA -> g_combined
    for (int i = 0; i < Tt; i++) {
        gemm128_nn<ACT_NONE><<<dim3(H3 / 128, BS / 128), 256>>>(
            x, qkv_W + (size_t)i * Hh * H3, qkv_b + (size_t)i * H3, qkv,
            Hh, Hh, H3, H3, 1.0f);
        attn_scores_kernel<<<dim3(4, 4, Bb * NHh), 256>>>(qkv, scores);
        softmax_mask_kernel<<<Bb * NHh * Ss, 256>>>(scores, mask + (size_t)i * Bb * Ss * Ss);
        attn_pv_kernel<<<dim3(1, 8, Bb * NHh), 256>>>(scores, qkv, att);
        gemm128_nn<ACT_NONE><<<dim3(Hh / 128, BS / 128), 256>>>(
            att, attn_out_W + (size_t)i * Hh * Hh, attn_out_b + (size_t)i * Hh,
            combined + (size_t)i * Hh,
            Hh, Hh, Hh, Tt * Hh, 1.0f);
    }

    // 3) mixer
    gemm128_nn<ACT_NONE><<<dim3(Hh / 128, BS / 128), 256>>>(
        combined, mixer_W1, mixer_b1, t1, Tt * Hh, Tt * Hh, Hh, Hh, 1.0f);
    ln_kernel<true><<<BS, 256>>>(t1, nullptr, mixer_ln_g, mixer_ln_b, t0, Hh);
    gemm_nn<ACT_NONE><<<dim3(1, BS / 64), 256>>>(
        t0, mixer_W2, mixer_b2, logits, BS, Tt, Hh, Hh, Tt, Tt, 1.0f);
    weighted_kernel<<<(BS * Hh) / 256, 256>>>(combined, logits, weighted);

    // 4) post-norm transformer encoder layer
    gemm128_nn<ACT_NONE><<<dim3(H3 / 128, BS / 128), 256>>>(
        weighted, el_qkv_W, el_qkv_b, qkv, Hh, Hh, H3, H3, 1.0f);
    attn_scores_kernel<<<dim3(4, 4, Bb * NHh), 256>>>(qkv, scores);
    softmax_mask_kernel<<<Bb * NHh * Ss, 256>>>(scores, nullptr);
    attn_pv_kernel<<<dim3(1, 8, Bb * NHh), 256>>>(scores, qkv, att);
    gemm128_nn<ACT_NONE><<<dim3(Hh / 128, BS / 128), 256>>>(
        att, el_out_W, el_out_b, sa, Hh, Hh, Hh, Hh, 1.0f);
    ln_kernel<false><<<BS, 256>>>(weighted, sa, el_ln1_g, el_ln1_b, h1, Hh);
    gemm128_nn<ACT_GELU><<<dim3(2048 / 128, BS / 128), 256>>>(
        h1, el_ff_W1, el_ff_b1, t0, Hh, Hh, 2048, 2048, 1.0f);
    gemm128_nn<ACT_NONE><<<dim3(Hh / 128, BS / 128), 256>>>(
        t0, el_ff_W2, el_ff_b2, t1, 2048, 2048, Hh, Hh, 1.0f);
    ln_kernel<false><<<BS, 256>>>(h1, t1, el_ln2_g, el_ln2_b, h2, Hh);

    // 5) output projection + final LN -> d_out
    gemm128_nn<ACT_NONE><<<dim3(Hh / 128, BS / 128), 256>>>(
        h2, op_W, op_b, t1, Hh, Hh, Hh, Hh, 1.0f);
    ln_kernel<false><<<BS, 256>>>(t1, nullptr, op_ln_g, op_ln_b, out, Hh);
}

// round 5
// speedup vs baseline: 1.7540x; 1.7540x over previous
#include <cuda_runtime.h>
#include <cuda_bf16.h>
#include <math.h>

// ---------------- problem constants ----------------
#define Bb 4
#define Ss 512
#define Hh 512
#define NHh 8
#define DHh 64
#define Tt 3
#define DTS 170
#define BS 2048            // B*S
#define H3 1536            // 3*H
#define EPSF 1e-5f

#define NBIN 4096
#define AM_MAX 6.0f

// ---------------- static scratch ----------------
__device__ float g_mask[(size_t)Tt * Bb * Ss * Ss];
__device__ float g_table[Tt * 3 * (NBIN + 1)];
__device__ float g_qkv[(size_t)BS * H3];
__device__ float g_scores[(size_t)Bb * NHh * Ss * Ss];
__device__ float g_att[(size_t)BS * Hh];
__device__ float g_combined[(size_t)BS * Tt * Hh];
__device__ float g_t0[(size_t)BS * 2048];
__device__ float g_t1[(size_t)BS * Hh];
__device__ float g_logits[(size_t)BS * 4];
__device__ float g_weighted[(size_t)BS * Hh];
__device__ float g_sa[(size_t)BS * Hh];
__device__ float g_h1[(size_t)BS * Hh];
__device__ float g_h2[(size_t)BS * Hh];

__device__ __forceinline__ float gelu_exact(float x) {
    return 0.5f * x * (1.0f + erff(x * 0.70710678118654752f));
}

enum { ACT_NONE = 0, ACT_GELU = 1 };

// ================= 64x64x16 SGEMM, 4x4 microtile, 256 threads =================
template <bool TB, int ACT>
__device__ __forceinline__ void gemm_body(
    const float* __restrict__ A, const float* __restrict__ B,
    const float* __restrict__ bias, float* __restrict__ C,
    int M, int N, int K, int lda, int ldb, int ldc, float alpha,
    int bm, int bn)
{
    __shared__ float As[16][68];
    __shared__ float Bs[16][68];
    const int tid = threadIdx.x;
    const int tx  = tid & 15;
    const int ty  = tid >> 4;

    float acc[4][4];
#pragma unroll
    for (int i = 0; i < 4; i++)
#pragma unroll
        for (int j = 0; j < 4; j++) acc[i][j] = 0.f;

    for (int k0 = 0; k0 < K; k0 += 16) {
        {
            int r  = tid >> 2;
            int kq = (tid & 3) << 2;
            int gr = bm + r;
            float4 a = make_float4(0.f, 0.f, 0.f, 0.f);
            if (gr < M)
                a = *(const float4*)(A + (size_t)gr * lda + k0 + kq);
            As[kq + 0][r] = a.x;
            As[kq + 1][r] = a.y;
            As[kq + 2][r] = a.z;
            As[kq + 3][r] = a.w;
        }
        if (TB) {
            int r  = tid >> 2;
            int kq = (tid & 3) << 2;
            int gn = bn + r;
            float4 bvv = make_float4(0.f, 0.f, 0.f, 0.f);
            if (gn < N)
                bvv = *(const float4*)(B + (size_t)gn * ldb + k0 + kq);
            Bs[kq + 0][r] = bvv.x;
            Bs[kq + 1][r] = bvv.y;
            Bs[kq + 2][r] = bvv.z;
            Bs[kq + 3][r] = bvv.w;
        } else {
            int kk = tid >> 4;
            int n4 = (tid & 15) << 2;
            int gn = bn + n4;
            float t0 = 0.f, t1 = 0.f, t2 = 0.f, t3 = 0.f;
            if (gn + 3 < N) {
                float4 bvv = *(const float4*)(B + (size_t)(k0 + kk) * ldb + gn);
                t0 = bvv.x; t1 = bvv.y; t2 = bvv.z; t3 = bvv.w;
            } else {
                if (gn + 0 < N) t0 = B[(size_t)(k0 + kk) * ldb + gn + 0];
                if (gn + 1 < N) t1 = B[(size_t)(k0 + kk) * ldb + gn + 1];
                if (gn + 2 < N) t2 = B[(size_t)(k0 + kk) * ldb + gn + 2];
                if (gn + 3 < N) t3 = B[(size_t)(k0 + kk) * ldb + gn + 3];
            }
            Bs[kk][n4 + 0] = t0;
            Bs[kk][n4 + 1] = t1;
            Bs[kk][n4 + 2] = t2;
            Bs[kk][n4 + 3] = t3;
        }
        __syncthreads();

#pragma unroll
        for (int kk = 0; kk < 16; kk++) {
            float4 av = *(const float4*)&As[kk][ty << 2];
            float4 bvv = *(const float4*)&Bs[kk][tx << 2];
            acc[0][0] += av.x * bvv.x; acc[0][1] += av.x * bvv.y;
            acc[0][2] += av.x * bvv.z; acc[0][3] += av.x * bvv.w;
            acc[1][0] += av.y * bvv.x; acc[1][1] += av.y * bvv.y;
            acc[1][2] += av.y * bvv.z; acc[1][3] += av.y * bvv.w;
            acc[2][0] += av.z * bvv.x; acc[2][1] += av.z * bvv.y;
            acc[2][2] += av.z * bvv.z; acc[2][3] += av.z * bvv.w;
            acc[3][0] += av.w * bvv.x; acc[3][1] += av.w * bvv.y;
            acc[3][2] += av.w * bvv.z; acc[3][3] += av.w * bvv.w;
        }
        __syncthreads();
    }

#pragma unroll
    for (int i = 0; i < 4; i++) {
        int gm = bm + (ty << 2) + i;
        if (gm >= M) continue;
#pragma unroll
        for (int j = 0; j < 4; j++) {
            int gn = bn + (tx << 2) + j;
            if (gn >= N) continue;
            float v = acc[i][j] * alpha;
            if (bias) v += bias[gn];
            if (ACT == ACT_GELU) v = gelu_exact(v);
            C[(size_t)gm * ldc + gn] = v;
        }
    }
}

template <int ACT>
__global__ void gemm_nn(const float* __restrict__ A, const float* __restrict__ B,
                        const float* __restrict__ bias, float* __restrict__ C,
                        int M, int N, int K, int lda, int ldb, int ldc, float alpha)
{
    gemm_body<false, ACT>(A, B, bias, C, M, N, K, lda, ldb, ldc, alpha,
                          blockIdx.y * 64, blockIdx.x * 64);
}

__global__ void attn_scores_kernel(const float* __restrict__ qkv, float* __restrict__ scores)
{
    int z = blockIdx.z;
    int b = z >> 3, h = z & 7;
    const float* Aq = qkv + (size_t)b * Ss * H3 + h * DHh;
    const float* Bk = qkv + (size_t)b * Ss * H3 + Hh + h * DHh;
    float* C = scores + (size_t)z * Ss * Ss;
    gemm_body<true, ACT_NONE>(Aq, Bk, nullptr, C, Ss, Ss, DHh, H3, H3, Ss, 0.125f,
                              blockIdx.y * 64, blockIdx.x * 64);
}

__global__ void attn_pv_kernel(const float* __restrict__ P, const float* __restrict__ qkv,
                               float* __restrict__ O)
{
    int z = blockIdx.z;
    int b = z >> 3, h = z & 7;
    const float* Ap = P + (size_t)z * Ss * Ss;
    const float* Bv = qkv + (size_t)b * Ss * H3 + 2 * Hh + h * DHh;
    float* C = O + (size_t)b * Ss * Hh + h * DHh;
    gemm_body<false, ACT_NONE>(Ap, Bv, nullptr, C, Ss, DHh, Ss, Ss, H3, Hh, 1.0f,
                               blockIdx.y * 64, blockIdx.x * 64);
}

// ================= mask table build: one warp per (i, dirIdx, bin) entry =================
__global__ void mask_table_kernel(const float* __restrict__ enc_W, const float* __restrict__ enc_b,
                                  const float* __restrict__ lng, const float* __restrict__ lnb,
                                  float* __restrict__ table)
{
    __shared__ float sW0[Tt][DTS], sW1[Tt][DTS], sB[Tt][DTS], sG[Tt][DTS], sBe[Tt][DTS];
    for (int idx = threadIdx.x; idx < Tt * DTS; idx += blockDim.x) {
        int i = idx / DTS, d = idx % DTS;
        sW0[i][d] = enc_W[i * 2 * DTS + d];
        sW1[i][d] = enc_W[i * 2 * DTS + DTS + d];
        sB[i][d]  = enc_b[idx];
        sG[i][d]  = lng[idx];
        sBe[i][d] = lnb[idx];
    }
    __syncthreads();

    int warp = blockIdx.x * (blockDim.x >> 5) + (threadIdx.x >> 5);
    int lane = threadIdx.x & 31;
    const int entries = Tt * 3 * (NBIN + 1);
    if (warp >= entries) return;

    int bin = warp % (NBIN + 1);
    int rem = warp / (NBIN + 1);
    int dirIdx = rem % 3;          // 0:-1, 1:0, 2:+1
    int i = rem / 3;               // timescale

    float dir = (float)(dirIdx - 1);
    float am  = (float)bin * (AM_MAX / NBIN);
    float scale = (i == 0) ? 1.0f : (i == 1 ? 0.1f : 0.01f);
    float mag = am * scale;

    float v[6];
    float s1 = 0.f, s2 = 0.f;
#pragma unroll
    for (int j = 0; j < 6; j++) {
        int d = lane + 32 * j;
        float val = 0.f;
        if (d < DTS) val = dir * sW0[i][d] + mag * sW1[i][d] + sB[i][d];
        v[j] = val;
        s1 += val;
        s2 += val * val;
    }
#pragma unroll
    for (int o = 16; o > 0; o >>= 1) {
        s1 += __shfl_xor_sync(0xffffffffu, s1, o);
        s2 += __shfl_xor_sync(0xffffffffu, s2, o);
    }
    float mean = s1 * (1.0f / DTS);
    float var  = s2 * (1.0f / DTS) - mean * mean;
    float rstd = rsqrtf(var + EPSF);
    float g = 0.f;
#pragma unroll
    for (int j = 0; j < 6; j++) {
        int d = lane + 32 * j;
        if (d < DTS) {
            float t = (v[j] - mean) * rstd * sG[i][d] + sBe[i][d];
            g += gelu_exact(t);
        }
    }
#pragma unroll
    for (int o = 16; o > 0; o >>= 1) g += __shfl_xor_sync(0xffffffffu, g, o);
    if (lane == 0)
        table[warp] = g * (1.0f / DTS);
}

// ================= per-pair mask via table interpolation =================
__global__ void mask_interp_kernel(const float* __restrict__ ts,
                                   const float* __restrict__ table,
                                   float* __restrict__ mask)
{
    int idx = blockIdx.x * blockDim.x + threadIdx.x;     // over Bb*Ss*Ss
    int k = idx & (Ss - 1);
    int q = (idx >> 9) & (Ss - 1);
    int b = idx >> 18;

    float dt = ts[b * Ss + q] - ts[b * Ss + k];
    int dirIdx = (dt > 0.f) ? 2 : ((dt < 0.f) ? 0 : 1);
    float am = log1pf(fabsf(dt) * (1.0f / 3600.0f));
    float u = am * ((float)NBIN / AM_MAX);
    u = fminf(fmaxf(u, 0.f), (float)NBIN - 1e-4f);
    int i0 = (int)u;
    float f = u - (float)i0;

#pragma unroll
    for (int i = 0; i < Tt; i++) {
        const float* tb = table + (i * 3 + dirIdx) * (NBIN + 1);
        float a = tb[i0];
        float bv = tb[i0 + 1];
        mask[(size_t)i * (Bb * Ss * Ss) + idx] = a + f * (bv - a);
    }
}

// ================= row softmax with optional additive mask (in place) =================
__global__ void softmax_mask_kernel(float* __restrict__ scores, const float* __restrict__ mask)
{
    __shared__ float sred[8];
    __shared__ float sval;
    int row = blockIdx.x;
    int tid = threadIdx.x;
    float* sr = scores + (size_t)row * Ss;

    float m0 = 0.f, m1 = 0.f;
    if (mask) {
        int q = row & (Ss - 1);
        int b = row >> 12;
        const float* mr = mask + ((size_t)(b * Ss + q)) * Ss;
        m0 = mr[tid];
        m1 = mr[tid + 256];
    }
    float v0 = sr[tid] + m0;
    float v1 = sr[tid + 256] + m1;

    float mx = fmaxf(v0, v1);
#pragma unroll
    for (int o = 16; o > 0; o >>= 1) mx = fmaxf(mx, __shfl_xor_sync(0xffffffffu, mx, o));
    if ((tid & 31) == 0) sred[tid >> 5] = mx;
    __syncthreads();
    if (tid == 0) {
        float m = sred[0];
        for (int i = 1; i < 8; i++) m = fmaxf(m, sred[i]);
        sval = m;
    }
    __syncthreads();
    mx = sval;

    float e0 = __expf(v0 - mx), e1 = __expf(v1 - mx);
    float s = e0 + e1;
#pragma unroll
    for (int o = 16; o > 0; o >>= 1) s += __shfl_xor_sync(0xffffffffu, s, o);
    if ((tid & 31) == 0) sred[tid >> 5] = s;
    __syncthreads();
    if (tid == 0) {
        float t = 0.f;
        for (int i = 0; i < 8; i++) t += sred[i];
        sval = t;
    }
    __syncthreads();
    float inv = 1.0f / sval;
    sr[tid]       = e0 * inv;
    sr[tid + 256] = e1 * inv;
}

// ================= LayerNorm (+optional residual, +optional gelu) =================
template <bool GELU>
__global__ void ln_kernel(const float* __restrict__ x, const float* __restrict__ res,
                          const float* __restrict__ g, const float* __restrict__ b,
                          float* __restrict__ y, int width)
{
    __shared__ float sred[8], sred2[8];
    __shared__ float smv[2];
    int row = blockIdx.x, tid = threadIdx.x;
    const float* xr = x + (size_t)row * width;
    const float* rr = res ? res + (size_t)row * width : nullptr;

    float s1 = 0.f, s2 = 0.f;
    for (int c = tid; c < width; c += blockDim.x) {
        float v = xr[c] + (rr ? rr[c] : 0.f);
        s1 += v;
        s2 += v * v;
    }
#pragma unroll
    for (int o = 16; o > 0; o >>= 1) {
        s1 += __shfl_xor_sync(0xffffffffu, s1, o);
        s2 += __shfl_xor_sync(0xffffffffu, s2, o);
    }
    if ((tid & 31) == 0) { sred[tid >> 5] = s1; sred2[tid >> 5] = s2; }
    __syncthreads();
    if (tid == 0) {
        float a = 0.f, c2 = 0.f;
        int nw = blockDim.x >> 5;
        for (int i = 0; i < nw; i++) { a += sred[i]; c2 += sred2[i]; }
        float mean = a / width;
        float var  = c2 / width - mean * mean;
        smv[0] = mean;
        smv[1] = rsqrtf(var + EPSF);
    }
    __syncthreads();
    float mean = smv[0], rstd = smv[1];
    for (int c = tid; c < width; c += blockDim.x) {
        float v = xr[c] + (rr ? rr[c] : 0.f);
        float t = (v - mean) * rstd * g[c] + b[c];
        if (GELU) t = gelu_exact(t);
        y[(size_t)row * width + c] = t;
    }
}

// ================= mixer softmax-weighted combine =================
__global__ void weighted_kernel(const float* __restrict__ combined,
                                const float* __restrict__ logits,
                                float* __restrict__ out)
{
    int idx = blockIdx.x * blockDim.x + threadIdx.x;
    int r = idx >> 9;
    int c = idx & (Hh - 1);
    float l0 = logits[r * 3 + 0];
    float l1 = logits[r * 3 + 1];
    float l2 = logits[r * 3 + 2];
    float mx = fmaxf(l0, fmaxf(l1, l2));
    float e0 = expf(l0 - mx), e1 = expf(l1 - mx), e2 = expf(l2 - mx);
    float inv = 1.0f / (e0 + e1 + e2);
    const float* cr = combined + (size_t)r * (Tt * Hh);
    out[idx] = (e0 * cr[c] + e1 * cr[Hh + c] + e2 * cr[2 * Hh + c]) * inv;
}

// ================= host-side orchestration =================
extern "C" void kernel_launch(void* const* d_in, const int* in_sizes, int n_in,
                              void* d_out, int out_size)
{
    const float* x          = (const float*)d_in[0];
    const float* ts         = (const float*)d_in[1];
    const float* enc_W      = (const float*)d_in[2];
    const float* enc_b      = (const float*)d_in[3];
    const float* enc_ln_g   = (const float*)d_in[4];
    const float* enc_ln_b   = (const float*)d_in[5];
    const float* qkv_W      = (const float*)d_in[6];
    const float* qkv_b      = (const float*)d_in[7];
    const float* attn_out_W = (const float*)d_in[8];
    const float* attn_out_b = (const float*)d_in[9];
    const float* mixer_W1   = (const float*)d_in[10];
    const float* mixer_b1   = (const float*)d_in[11];
    const float* mixer_ln_g = (const float*)d_in[12];
    const float* mixer_ln_b = (const float*)d_in[13];
    const float* mixer_W2   = (const float*)d_in[14];
    const float* mixer_b2   = (const float*)d_in[15];
    const float* el_qkv_W   = (const float*)d_in[16];
    const float* el_qkv_b   = (const float*)d_in[17];
    const float* el_out_W   = (const float*)d_in[18];
    const float* el_out_b   = (const float*)d_in[19];
    const float* el_ln1_g   = (const float*)d_in[20];
    const float* el_ln1_b   = (const float*)d_in[21];
    const float* el_ff_W1   = (const float*)d_in[22];
    const float* el_ff_b1   = (const float*)d_in[23];
    const float* el_ff_W2   = (const float*)d_in[24];
    const float* el_ff_b2   = (const float*)d_in[25];
    const float* el_ln2_g   = (const float*)d_in[26];
    const float* el_ln2_b   = (const float*)d_in[27];
    const float* op_W       = (const float*)d_in[28];
    const float* op_b       = (const float*)d_in[29];
    const float* op_ln_g    = (const float*)d_in[30];
    const float* op_ln_b    = (const float*)d_in[31];
    float* out = (float*)d_out;

    float *mask, *table, *qkv, *scores, *att, *combined, *t0, *t1, *logits, *weighted, *sa, *h1, *h2;
    cudaGetSymbolAddress((void**)&mask, g_mask);
    cudaGetSymbolAddress((void**)&table, g_table);
    cudaGetSymbolAddress((void**)&qkv, g_qkv);
    cudaGetSymbolAddress((void**)&scores, g_scores);
    cudaGetSymbolAddress((void**)&att, g_att);
    cudaGetSymbolAddress((void**)&combined, g_combined);
    cudaGetSymbolAddress((void**)&t0, g_t0);
    cudaGetSymbolAddress((void**)&t1, g_t1);
    cudaGetSymbolAddress((void**)&logits, g_logits);
    cudaGetSymbolAddress((void**)&weighted, g_weighted);
    cudaGetSymbolAddress((void**)&sa, g_sa);
    cudaGetSymbolAddress((void**)&h1, g_h1);
    cudaGetSymbolAddress((void**)&h2, g_h2);

    // 1) mask table (tiny) then per-pair interpolation
    {
        int entries = Tt * 3 * (NBIN + 1);
        int warps_per_block = 8;
        int blocks = (entries + warps_per_block - 1) / warps_per_block;
        mask_table_kernel<<<blocks, 256>>>(enc_W, enc_b, enc_ln_g, enc_ln_b, table);
        mask_interp_kernel<<<(Bb * Ss * Ss) / 256, 256>>>(ts, table, mask);
    }

    // 2) per-timescale MHA -> g_combined
    for (int i = 0; i < Tt; i++) {
        gemm_nn<ACT_NONE><<<dim3(H3 / 64, BS / 64), 256>>>(
            x, qkv_W + (size_t)i * Hh * H3, qkv_b + (size_t)i * H3, qkv,
            BS, H3, Hh, Hh, H3, H3, 1.0f);
        attn_scores_kernel<<<dim3(8, 8, Bb * NHh), 256>>>(qkv, scores);
        softmax_mask_kernel<<<Bb * NHh * Ss, 256>>>(scores, mask + (size_t)i * Bb * Ss * Ss);
        attn_pv_kernel<<<dim3(1, 8, Bb * NHh), 256>>>(scores, qkv, att);
        gemm_nn<ACT_NONE><<<dim3(Hh / 64, BS / 64), 256>>>(
            att, attn_out_W + (size_t)i * Hh * Hh, attn_out_b + (size_t)i * Hh,
            combined + (size_t)i * Hh,
            BS, Hh, Hh, Hh, Hh, Tt * Hh, 1.0f);
    }

    // 3) mixer
    gemm_nn<ACT_NONE><<<dim3(Hh / 64, BS / 64), 256>>>(
        combined, mixer_W1, mixer_b1, t1, BS, Hh, Tt * Hh, Tt * Hh, Hh, Hh, 1.0f);
    ln_kernel<true><<<BS, 256>>>(t1, nullptr, mixer_ln_g, mixer_ln_b, t0, Hh);
    gemm_nn<ACT_NONE><<<dim3(1, BS / 64), 256>>>(
        t0, mixer_W2, mixer_b2, logits, BS, Tt, Hh, Hh, Tt, Tt, 1.0f);
    weighted_kernel<<<(BS * Hh) / 256, 256>>>(combined, logits, weighted);

    // 4) post-norm transformer encoder layer
    gemm_nn<ACT_NONE><<<dim3(H3 / 64, BS / 64), 256>>>(
        weighted, el_qkv_W, el_qkv_b, qkv, BS, H3, Hh, Hh, H3, H3, 1.0f);
    attn_scores_kernel<<<dim3(8, 8, Bb * NHh), 256>>>(qkv, scores);
    softmax_mask_kernel<<<Bb * NHh * Ss, 256>>>(scores, nullptr);
    attn_pv_kernel<<<dim3(1, 8, Bb * NHh), 256>>>(scores, qkv, att);
    gemm_nn<ACT_NONE><<<dim3(Hh / 64, BS / 64), 256>>>(
        att, el_out_W, el_out_b, sa, BS, Hh, Hh, Hh, Hh, Hh, 1.0f);
    ln_kernel<false><<<BS, 256>>>(weighted, sa, el_ln1_g, el_ln1_b, h1, Hh);
    gemm_nn<ACT_GELU><<<dim3(2048 / 64, BS / 64), 256>>>(
        h1, el_ff_W1, el_ff_b1, t0, BS, 2048, Hh, Hh, 2048, 2048, 1.0f);
    gemm_nn<ACT_NONE><<<dim3(Hh / 64, BS / 64), 256>>>(
        t0, el_ff_W2, el_ff_b2, t1, BS, Hh, 2048, 2048, Hh, Hh, 1.0f);
    ln_kernel<false><<<BS, 256>>>(h1, t1, el_ln2_g, el_ln2_b, h2, Hh);

    // 5) output projection + final LN -> d_out
    gemm_nn<ACT_NONE><<<dim3(Hh / 64, BS / 64), 256>>>(
        h2, op_W, op_b, t1, BS, Hh, Hh, Hh, Hh, Hh, 1.0f);
    ln_kernel<false><<<BS, 256>>>(t1, nullptr, op_ln_g, op_ln_b, out, Hh);
}